// round 6
// baseline (speedup 1.0000x reference)
#include <cuda_runtime.h>
#include <cuda_bf16.h>
#include <cstdint>

#define NN 32768
#define KK 4000
#define DD 128
#define CC 1000

#define BM 128             // rows per CTA
#define BN 64              // proxies per tile
#define NTILES 63          // ceil(4000/64)
#define KPAD (NTILES*BN)   // 4032
#define DDC 384            // concat dims: [x0|x1|x0] . [p0|p0|p1]
#define ROWB 768           // bytes per row (384 bf16)
#define KSTEPS 24          // 384/16

#define WMARG 0.02f        // candidate window >> approx error (~1e-4 worst)
#define CAP 24             // per-row candidate capacity

// ---------------- global scratch (static, no allocs) ----------------
__device__ float g_x2[NN];
__device__ float g_p2[KK];
__device__ int   g_idx[NN];
__device__ __align__(16) __nv_bfloat16 g_xc[NN * DDC];    // 24MB
__device__ __align__(16) __nv_bfloat16 g_pc[KPAD * DDC];  // 3MB
__device__ int g_candn[NN];
__device__ int g_candk[NN * CAP];

// ---------------- asm helpers (all base-PTX, no 'a' features) ----------------
__device__ __forceinline__ uint32_t smem_u32(const void* p) {
    uint32_t a;
    asm("{ .reg .u64 t; cvta.to.shared.u64 t, %1; cvt.u32.u64 %0, t; }" : "=r"(a) : "l"(p));
    return a;
}
__device__ __forceinline__ void ldsm4(uint32_t addr, uint32_t& r0, uint32_t& r1,
                                      uint32_t& r2, uint32_t& r3) {
    asm volatile("ldmatrix.sync.aligned.m8n8.x4.shared.b16 {%0,%1,%2,%3}, [%4];"
        : "=r"(r0), "=r"(r1), "=r"(r2), "=r"(r3) : "r"(addr));
}
__device__ __forceinline__ void mma16816(float* c, uint32_t a0, uint32_t a1, uint32_t a2,
                                         uint32_t a3, uint32_t b0, uint32_t b1) {
    asm volatile("mma.sync.aligned.m16n8k16.row.col.f32.bf16.bf16.f32 "
        "{%0,%1,%2,%3}, {%4,%5,%6,%7}, {%8,%9}, {%0,%1,%2,%3};"
        : "+f"(c[0]), "+f"(c[1]), "+f"(c[2]), "+f"(c[3])
        : "r"(a0), "r"(a1), "r"(a2), "r"(a3), "r"(b0), "r"(b1));
}
__device__ __forceinline__ void cpa16(uint32_t dst, const void* src) {
    asm volatile("cp.async.cg.shared.global [%0], [%1], 16;" :: "r"(dst), "l"(src));
}
#define CP_COMMIT() asm volatile("cp.async.commit_group;")
#define CP_WAIT(n)  asm volatile("cp.async.wait_group %0;" :: "n"(n))

// ---------------- smem layout ----------------
#define SO_A   0
#define SO_B   98304          // 2 bufs x 49152
#define B_BUF  49152
#define SO_P2  196608         // 2 x 64 floats
#define SMEM_TOT 197120
// reduction scratch reused inside B region after the mainloop:
#define SO_RV  (SO_B)         // 128*8 float
#define SO_RI  (SO_B + 4096)  // 128*8 int
#define SO_BVG (SO_B + 8192)  // 128 float
#define SO_BIG (SO_B + 8704)  // 128 int

// ---------------- prep: 2-way bf16 split, concat layout ----------------
__global__ void split_x_kernel(const float* __restrict__ x) {
    int c = blockIdx.x * 256 + threadIdx.x;        // NN*16 chunks of 8 dims
    int row = c >> 4, d0 = (c & 15) << 3;
    float v[8];
    *(float4*)&v[0] = *(const float4*)(x + (size_t)row * DD + d0);
    *(float4*)&v[4] = *(const float4*)(x + (size_t)row * DD + d0 + 4);
    union { __nv_bfloat16 h[8]; uint4 u; } u0, u1;
#pragma unroll
    for (int i = 0; i < 8; i++) {
        __nv_bfloat16 h0 = __float2bfloat16(v[i]);
        u0.h[i] = h0;
        u1.h[i] = __float2bfloat16(v[i] - __bfloat162float(h0));
    }
    __nv_bfloat16* base = g_xc + (size_t)row * DDC;
    *(uint4*)(base + d0)       = u0.u;   // x0
    *(uint4*)(base + 128 + d0) = u1.u;   // x1
    *(uint4*)(base + 256 + d0) = u0.u;   // x0 again
}

__global__ void split_p_kernel(const float* __restrict__ p) {
    int c = blockIdx.x * 256 + threadIdx.x;        // KPAD*16 chunks
    int k = c >> 4, d0 = (c & 15) << 3;
    float v[8];
    if (k < KK) {
        *(float4*)&v[0] = *(const float4*)(p + (size_t)k * DD + d0);
        *(float4*)&v[4] = *(const float4*)(p + (size_t)k * DD + d0 + 4);
    } else {
#pragma unroll
        for (int i = 0; i < 8; i++) v[i] = 0.f;
    }
    union { __nv_bfloat16 h[8]; uint4 u; } u0, u1;
#pragma unroll
    for (int i = 0; i < 8; i++) {
        __nv_bfloat16 h0 = __float2bfloat16(v[i]);
        u0.h[i] = h0;
        u1.h[i] = __float2bfloat16(v[i] - __bfloat162float(h0));
    }
    __nv_bfloat16* base = g_pc + (size_t)k * DDC;
    *(uint4*)(base + d0)       = u0.u;   // p0
    *(uint4*)(base + 128 + d0) = u0.u;   // p0 again
    *(uint4*)(base + 256 + d0) = u1.u;   // p1
}

// ---------------- row squared norms ----------------
__global__ void row_norm_kernel(const float* __restrict__ A, float* __restrict__ out, int rows) {
    int row  = blockIdx.x * 8 + (threadIdx.x >> 5);
    int lane = threadIdx.x & 31;
    if (row >= rows) return;
    const float* a = A + (size_t)row * DD;
    float s = 0.f;
#pragma unroll
    for (int i = 0; i < DD / 32; i++) { float v = a[lane + 32 * i]; s = fmaf(v, v, s); }
#pragma unroll
    for (int o = 16; o > 0; o >>= 1) s += __shfl_down_sync(0xffffffffu, s, o);
    if (lane == 0) out[row] = s;
}

// ---------------- main mma.sync argmin ----------------
__device__ __forceinline__ void issue_B(uint32_t sb, char* smp, int tile, int buf, int tid) {
    const char* src = (const char*)g_pc + (size_t)tile * BN * ROWB;
    uint32_t base = sb + SO_B + buf * B_BUF;
#pragma unroll
    for (int j = 0; j < 12; j++) {             // 3072 16B chunks / 256 thr
        int i = tid + 256 * j;
        int r = i / 48, c = i % 48;
        cpa16(base + r * ROWB + ((c ^ (r & 7)) << 4), src + r * ROWB + c * 16);
    }
    if (tid < BN) {
        int k = tile * BN + tid;
        ((float*)(smp + SO_P2))[buf * BN + tid] = (k < KK) ? g_p2[k] : 3.0e38f;
    }
}

extern __shared__ char smx[];

__global__ __launch_bounds__(256, 1) void mma_argmin_kernel() {
    char* smp = smx;
    uint32_t sb = smem_u32(smx);
    int tid = threadIdx.x, lane = tid & 31, w = tid >> 5;
    int wm = w & 3, wn = w >> 2;               // 4x2 warp grid: 32 rows x 32 cols each
    int rowBase = blockIdx.x * BM;

    // A tile: 6144 16B chunks (96KB), swizzled
    {
        const char* src = (const char*)g_xc + (size_t)rowBase * ROWB;
#pragma unroll
        for (int j = 0; j < 24; j++) {
            int i = tid + 256 * j;
            int r = i / 48, c = i % 48;
            cpa16(sb + SO_A + r * ROWB + ((c ^ (r & 7)) << 4), src + r * ROWB + c * 16);
        }
    }
    issue_B(sb, smp, 0, 0, tid);
    CP_COMMIT();

    float x2r[4];
#pragma unroll
    for (int s = 0; s < 4; s++) x2r[s] = g_x2[rowBase + 32 * wm + (lane >> 2) + 8 * s];

    // fragment address bases
    uint32_t aAddr[2]; int aXor[2];
    uint32_t bOff[2];  int bXor[2];
    int akc = lane >> 4;            // A k-chunk select (+0/+1)
    int bkh = (lane >> 3) & 1;      // B k-half select
#pragma unroll
    for (int mf = 0; mf < 2; mf++) {
        int rA = 32 * wm + 16 * mf + (lane & 15);
        aAddr[mf] = sb + SO_A + rA * ROWB;
        aXor[mf] = rA & 7;
    }
#pragma unroll
    for (int q = 0; q < 2; q++) {
        int nB = 32 * wn + 16 * q + (lane & 7) + ((lane >> 4) << 3);
        bOff[q] = nB * ROWB;
        bXor[q] = nB & 7;
    }

    float bestv[4]; int besti[4]; int res[4][2]; int rcnt[4];
#pragma unroll
    for (int s = 0; s < 4; s++) { bestv[s] = 3.0e38f; besti[s] = 0; rcnt[s] = 0; }

    for (int t = 0; t < NTILES; t++) {
        int b = t & 1;
        if (t + 1 < NTILES) {
            issue_B(sb, smp, t + 1, 1 - b, tid);
            CP_COMMIT();
            CP_WAIT(1);
        } else {
            CP_WAIT(0);
        }
        __syncthreads();

        float acc[2][4][4];
#pragma unroll
        for (int i = 0; i < 2; i++)
#pragma unroll
            for (int j = 0; j < 4; j++)
#pragma unroll
                for (int q = 0; q < 4; q++) acc[i][j][q] = 0.f;

        uint32_t bbase = sb + SO_B + b * B_BUF;
#pragma unroll 8
        for (int ks = 0; ks < KSTEPS; ks++) {
            uint32_t av[8], bv[8];
            ldsm4(aAddr[0] + (uint32_t)(((2 * ks + akc) ^ aXor[0]) << 4), av[0], av[1], av[2], av[3]);
            ldsm4(aAddr[1] + (uint32_t)(((2 * ks + akc) ^ aXor[1]) << 4), av[4], av[5], av[6], av[7]);
            ldsm4(bbase + bOff[0] + (uint32_t)(((2 * ks + bkh) ^ bXor[0]) << 4), bv[0], bv[1], bv[2], bv[3]);
            ldsm4(bbase + bOff[1] + (uint32_t)(((2 * ks + bkh) ^ bXor[1]) << 4), bv[4], bv[5], bv[6], bv[7]);
#pragma unroll
            for (int mf = 0; mf < 2; mf++)
#pragma unroll
                for (int nf = 0; nf < 4; nf++)
                    mma16816(acc[mf][nf], av[mf * 4], av[mf * 4 + 1], av[mf * 4 + 2],
                             av[mf * 4 + 3], bv[nf * 2], bv[nf * 2 + 1]);
        }

        // epilogue: scores + running argmin with candidate window
        const float* p2s = (const float*)(smp + SO_P2) + b * BN;
#pragma unroll
        for (int nf = 0; nf < 4; nf++) {
            int cl = 32 * wn + 8 * nf + 2 * (lane & 3);
            float pp0 = p2s[cl], pp1 = p2s[cl + 1];
            int k0 = t * BN + cl;
#pragma unroll
            for (int s = 0; s < 4; s++) {
                float d0 = acc[s >> 1][nf][(s & 1) * 2];
                float d1 = acc[s >> 1][nf][(s & 1) * 2 + 1];
                float s0 = fmaf(-2.f, d0, x2r[s] + pp0);
                float s1 = fmaf(-2.f, d1, x2r[s] + pp1);
                if (s0 < bestv[s]) {
                    if (bestv[s] <= s0 + WMARG) { if (rcnt[s] < 2) res[s][rcnt[s]] = besti[s]; rcnt[s]++; }
                    bestv[s] = s0; besti[s] = k0;
                } else if (s0 <= bestv[s] + WMARG) {
                    if (rcnt[s] < 2) res[s][rcnt[s]] = k0; rcnt[s]++;
                }
                if (s1 < bestv[s]) {
                    if (bestv[s] <= s1 + WMARG) { if (rcnt[s] < 2) res[s][rcnt[s]] = besti[s]; rcnt[s]++; }
                    bestv[s] = s1; besti[s] = k0 + 1;
                } else if (s1 <= bestv[s] + WMARG) {
                    if (rcnt[s] < 2) res[s][rcnt[s]] = k0 + 1; rcnt[s]++;
                }
            }
        }
        __syncthreads();
    }

    // ---- cross-thread reduction (8 entries per row) ----
    float* rv  = (float*)(smp + SO_RV);
    int*   ri  = (int*)(smp + SO_RI);
    float* bvg = (float*)(smp + SO_BVG);
    int*   big = (int*)(smp + SO_BIG);
#pragma unroll
    for (int s = 0; s < 4; s++) {
        int rl = 32 * wm + (lane >> 2) + 8 * s;
        int slot = wn * 4 + (lane & 3);
        rv[rl * 8 + slot] = bestv[s];
        ri[rl * 8 + slot] = besti[s];
    }
    __syncthreads();
    if (tid < BM) {
        float bv = 3.4e38f; int bi = 0x7fffffff;
#pragma unroll
        for (int j = 0; j < 8; j++) {
            float v = rv[tid * 8 + j]; int ix = ri[tid * 8 + j];
            if (v < bv || (v == bv && ix < bi)) { bv = v; bi = ix; }
        }
        g_idx[rowBase + tid] = bi;
        bvg[tid] = bv; big[tid] = bi;
    }
    __syncthreads();

    // ---- candidate append for exact fixup ----
#pragma unroll
    for (int s = 0; s < 4; s++) {
        int rl = 32 * wm + (lane >> 2) + 8 * s;
        int R = rowBase + rl;
        if (rcnt[s] > 2) {                         // thread-local overflow -> full scan
            atomicAdd(&g_candn[R], 1 << 20);
        } else {
            int win = big[rl];
            float bg = bvg[rl];
            for (int j = 0; j < rcnt[s]; j++) {
                int k = res[s][j];
                if (k != win) {
                    int pos = atomicAdd(&g_candn[R], 1);
                    if (pos < CAP) g_candk[R * CAP + pos] = k;
                }
            }
            if (bestv[s] <= bg + WMARG && besti[s] != win) {
                int pos = atomicAdd(&g_candn[R], 1);
                if (pos < CAP) g_candk[R * CAP + pos] = besti[s];
            }
        }
    }
}

// ---------------- exact fp32 fixup (same fmaf order as the rel_err-0 kernel) ----
__device__ __forceinline__ float exact_score(const float* __restrict__ x,
                                             const float* __restrict__ p,
                                             int row, int k, float x2) {
    const float* xr = x + (size_t)row * DD;
    const float* pr = p + (size_t)k * DD;
    float acc = 0.f;
#pragma unroll 8
    for (int d = 0; d < DD; d++) acc = fmaf(xr[d], pr[d], acc);
    return (x2 - 2.0f * acc) + g_p2[k];
}

__global__ void fixup_kernel(const float* __restrict__ x, const float* __restrict__ p) {
    int row = blockIdx.x * blockDim.x + threadIdx.x;
    if (row >= NN) return;
    int n = g_candn[row];
    if (n == 0) return;
    float x2 = g_x2[row];
    int bi = g_idx[row];
    float bv = exact_score(x, p, row, bi, x2);
    if (n > CAP) {             // dropped candidates -> full exact scan
        for (int k = 0; k < KK; k++) {
            float s = exact_score(x, p, row, k, x2);
            if (s < bv || (s == bv && k < bi)) { bv = s; bi = k; }
        }
    } else {
        for (int j = 0; j < n; j++) {
            int k = g_candk[row * CAP + j];
            float s = exact_score(x, p, row, k, x2);
            if (s < bv || (s == bv && k < bi)) { bv = s; bi = k; }
        }
    }
    g_idx[row] = bi;
}

// ---------------- gather ----------------
__global__ void gather_kernel(const float* __restrict__ x, const float* __restrict__ p,
                              const float* __restrict__ lab, float* __restrict__ out) {
    int row = blockIdx.x;
    int tid = threadIdx.x;
    int idx = g_idx[row];

    const float4* xr = (const float4*)(x + (size_t)row * DD);
    float4*       o0 = (float4*)(out + (size_t)row * DD);
    const float4* pr = (const float4*)(p + (size_t)idx * DD);
    float4*       o1 = (float4*)(out + (size_t)NN * DD + (size_t)row * DD);
    const float4* lr = (const float4*)(lab + (size_t)idx * CC);
    float4*       o2 = (float4*)(out + 2 * (size_t)NN * DD + (size_t)row * CC);

    if (tid < 32)       __stcs(o0 + tid,      xr[tid]);
    else if (tid < 64)  __stcs(o1 + tid - 32, pr[tid - 32]);
    for (int i = tid; i < CC / 4; i += blockDim.x) __stcs(o2 + i, lr[i]);
}

// ---------------- launch ----------------
extern "C" void kernel_launch(void* const* d_in, const int* in_sizes, int n_in,
                              void* d_out, int out_size) {
    const float* x   = (const float*)d_in[0];
    const float* p   = (const float*)d_in[1];
    const float* lab = (const float*)d_in[2];
    float* out = (float*)d_out;

    float *px2 = nullptr, *pp2 = nullptr; void* pcandn = nullptr;
    cudaGetSymbolAddress((void**)&px2, g_x2);
    cudaGetSymbolAddress((void**)&pp2, g_p2);
    cudaGetSymbolAddress(&pcandn, g_candn);

    cudaFuncSetAttribute(mma_argmin_kernel, cudaFuncAttributeMaxDynamicSharedMemorySize, SMEM_TOT);

    cudaMemsetAsync(pcandn, 0, NN * sizeof(int));
    split_x_kernel<<<NN * 16 / 256, 256>>>(x);
    split_p_kernel<<<KPAD * 16 / 256, 256>>>(p);
    row_norm_kernel<<<NN / 8, 256>>>(x, px2, NN);
    row_norm_kernel<<<(KK + 7) / 8, 256>>>(p, pp2, KK);
    mma_argmin_kernel<<<NN / BM, 256, SMEM_TOT>>>();
    fixup_kernel<<<NN / 256, 256>>>(x, p);
    gather_kernel<<<NN, 256>>>(x, p, lab, out);
}

// round 7
// speedup vs baseline: 9.5392x; 9.5392x over previous
#include <cuda_runtime.h>
#include <cstdint>

#define NN 32768
#define KK 4000
#define DD 128
#define CC 1000

#define BM 128
#define BN 128
#define NTILES 32          // ceil(4000/128) -> pad to 4096
#define KPAD (NTILES*BN)
#define TM 4
#define TN 8
#define TSA 132            // A smem stride (padded, 16B-aligned rows)
#define TSB 128            // B smem stride (verbatim cp.async layout)
#define NTHREADS 512

__device__ float g_x2[NN];
__device__ float g_p2[KPAD];
__device__ int   g_idx[NN];
// proxies pre-transposed per 128-tile: [tile][d][k_in_tile], zero-padded
__device__ __align__(16) float g_pT[KPAD * DD];

// ---------------- packed f32x2 helpers ----------------
__device__ __forceinline__ uint64_t ffma2(uint64_t a, uint64_t b, uint64_t c) {
    uint64_t d;
    asm("fma.rn.f32x2 %0, %1, %2, %3;" : "=l"(d) : "l"(a), "l"(b), "l"(c));
    return d;
}
__device__ __forceinline__ uint64_t pack2(float lo, float hi) {
    uint64_t d;
    asm("mov.b64 %0, {%1, %2};" : "=l"(d) : "f"(lo), "f"(hi));
    return d;
}
__device__ __forceinline__ float2 unpack2(uint64_t v) {
    float2 r;
    asm("mov.b64 {%0, %1}, %2;" : "=f"(r.x), "=f"(r.y) : "l"(v));
    return r;
}
__device__ __forceinline__ uint32_t smem_u32(const void* p) {
    uint32_t a;
    asm("{ .reg .u64 t; cvta.to.shared.u64 t, %1; cvt.u32.u64 %0, t; }" : "=r"(a) : "l"(p));
    return a;
}
__device__ __forceinline__ void cpa16(uint32_t dst, const void* src) {
    asm volatile("cp.async.cg.shared.global [%0], [%1], 16;" :: "r"(dst), "l"(src));
}
#define CP_COMMIT() asm volatile("cp.async.commit_group;")
#define CP_WAIT(n)  asm volatile("cp.async.wait_group %0;" :: "n"(n))

// ---------------- prep: proxies -> transposed tiles + pad sentinels --------
__global__ void prep_p_kernel(const float* __restrict__ p) {
    int c = blockIdx.x * 256 + threadIdx.x;   // KPAD*16 chunks of 8 dims
    int k = c >> 4, d0 = (c & 15) << 3;
    float v[8];
    if (k < KK) {
        *(float4*)&v[0] = *(const float4*)(p + (size_t)k * DD + d0);
        *(float4*)&v[4] = *(const float4*)(p + (size_t)k * DD + d0 + 4);
    } else {
#pragma unroll
        for (int i = 0; i < 8; i++) v[i] = 0.f;
        if (d0 == 0) g_p2[k] = 3.0e38f;       // pad sentinel (never wins argmin)
    }
    float* base = g_pT + (size_t)(k >> 7) * (BN * DD) + (k & 127);
#pragma unroll
    for (int i = 0; i < 8; i++) base[(size_t)(d0 + i) * BN] = v[i];
}

// ---------------- row squared norms ----------------
__global__ void row_norm_kernel(const float* __restrict__ A, float* __restrict__ out, int rows) {
    int row  = blockIdx.x * 8 + (threadIdx.x >> 5);
    int lane = threadIdx.x & 31;
    if (row >= rows) return;
    const float* a = A + (size_t)row * DD;
    float s = 0.f;
#pragma unroll
    for (int i = 0; i < DD / 32; i++) { float v = a[lane + 32 * i]; s = fmaf(v, v, s); }
#pragma unroll
    for (int o = 16; o > 0; o >>= 1) s += __shfl_down_sync(0xffffffffu, s, o);
    if (lane == 0) out[row] = s;
}

// ---------------- smem layout (floats) ----------------
#define FO_A   0                       // [DD][TSA] = 16896
#define FO_B   (DD * TSA)              // 2 x [DD][TSB] = 32768
#define FO_P2  (FO_B + 2 * DD * TSB)   // 2 x 128
#define FO_X2  (FO_P2 + 2 * BN)        // 128
#define SMEM_FLOATS (FO_X2 + BM)
#define SMEM_BYTES  (SMEM_FLOATS * 4)

extern __shared__ float sm[];

// ---------------- fused score-GEMM + running argmin ----------------
__global__ __launch_bounds__(NTHREADS, 1)
void argmin_kernel(const float* __restrict__ x) {
    float* As  = sm + FO_A;
    float* Bs  = sm + FO_B;
    float* p2s = sm + FO_P2;
    float* x2s = sm + FO_X2;
    uint32_t sbB = smem_u32(sm + FO_B);

    int tid = threadIdx.x;
    int tx  = tid & 15;      // proxy group (TN=8)
    int ty  = tid >> 4;      // row group   (TM=4)
    int rowBase = blockIdx.x * BM;

    // --- prologue: kick B tiles 0 and 1 via cp.async (verbatim 16B copies) ---
#pragma unroll
    for (int buf = 0; buf < 2; buf++) {
        const char* src = (const char*)(g_pT + (size_t)buf * (BN * DD));
        uint32_t dst = sbB + buf * (DD * TSB * 4);
#pragma unroll
        for (int j = 0; j < 8; j++) {
            int i = tid + NTHREADS * j;
            cpa16(dst + i * 16, src + i * 16);
        }
        CP_COMMIT();
        if (tid < BN) p2s[buf * BN + tid] = g_p2[buf * BN + tid];
    }

    // --- A tile: load + transpose once (amortized over 32 tiles) ---
    for (int i = tid; i < BM * DD / 4; i += NTHREADS) {
        int r = i >> 5;
        int c = (i & 31) << 2;
        float4 v = *(const float4*)(x + (size_t)(rowBase + r) * DD + c);
        As[(c + 0) * TSA + r] = v.x;
        As[(c + 1) * TSA + r] = v.y;
        As[(c + 2) * TSA + r] = v.z;
        As[(c + 3) * TSA + r] = v.w;
    }
    if (tid < BM) x2s[tid] = g_x2[rowBase + tid];
    __syncthreads();

    float x2r[TM];
#pragma unroll
    for (int i = 0; i < TM; i++) x2r[i] = x2s[ty * TM + i];

    float bestv[TM]; int besti[TM];
#pragma unroll
    for (int i = 0; i < TM; i++) { bestv[i] = 3.0e38f; besti[i] = 0; }

    const float* xb = As + ty * TM;

    for (int t = 0; t < NTILES; t++) {
        int b = t & 1;
        if (t == NTILES - 1) { CP_WAIT(0); } else { CP_WAIT(1); }
        __syncthreads();

        uint64_t acc[TM][TN / 2];
#pragma unroll
        for (int i = 0; i < TM; i++)
#pragma unroll
            for (int j = 0; j < TN / 2; j++) acc[i][j] = 0ull;

        const float* pb = Bs + b * (DD * TSB) + tx * TN;
#pragma unroll 2
        for (int d = 0; d < DD; d++) {
            float4     xa = *(const float4*)(xb + d * TSA);
            ulonglong2 pA = *(const ulonglong2*)(pb + d * TSB);
            ulonglong2 pB = *(const ulonglong2*)(pb + d * TSB + 4);
            uint64_t xs4[TM] = { pack2(xa.x, xa.x), pack2(xa.y, xa.y),
                                 pack2(xa.z, xa.z), pack2(xa.w, xa.w) };
            uint64_t pv[TN / 2] = { pA.x, pA.y, pB.x, pB.y };
#pragma unroll
            for (int i = 0; i < TM; i++)
#pragma unroll
                for (int j = 0; j < TN / 2; j++)
                    acc[i][j] = ffma2(xs4[i], pv[j], acc[i][j]);
        }

        // running argmin (k ascending per thread; strict '<' = first-min)
        const float* pp = p2s + b * BN + tx * TN;
#pragma unroll
        for (int j = 0; j < TN / 2; j++) {
            int kg = t * BN + tx * TN + 2 * j;
            float p0 = pp[2 * j], p1 = pp[2 * j + 1];
#pragma unroll
            for (int i = 0; i < TM; i++) {
                float2 dp = unpack2(acc[i][j]);
                float s0 = (x2r[i] - 2.0f * dp.x) + p0;
                float s1 = (x2r[i] - 2.0f * dp.y) + p1;
                if (s0 < bestv[i]) { bestv[i] = s0; besti[i] = kg; }
                if (s1 < bestv[i]) { bestv[i] = s1; besti[i] = kg + 1; }
            }
        }
        __syncthreads();    // everyone done reading buffer b

        if (t + 2 < NTILES) {   // refill buffer b with tile t+2
            const char* src = (const char*)(g_pT + (size_t)(t + 2) * (BN * DD));
            uint32_t dst = sbB + b * (DD * TSB * 4);
#pragma unroll
            for (int j = 0; j < 8; j++) {
                int i = tid + NTHREADS * j;
                cpa16(dst + i * 16, src + i * 16);
            }
            CP_COMMIT();
            if (tid < BN) p2s[b * BN + tid] = g_p2[(t + 2) * BN + tid];
        }
    }

    // --- cross-thread reduction: 16 candidates per row (reuse B region) ---
    float* redv = Bs;                     // [16][BM]
    int*   redi = (int*)(Bs + 16 * BM);   // [16][BM]
#pragma unroll
    for (int i = 0; i < TM; i++) {
        int row = ty * TM + i;
        redv[tx * BM + row] = bestv[i];
        redi[tx * BM + row] = besti[i];
    }
    __syncthreads();
    if (tid < BM) {
        float bv = 3.4e38f; int bi = 0x7fffffff;
#pragma unroll
        for (int t = 0; t < 16; t++) {
            float v  = redv[t * BM + tid];
            int   ix = redi[t * BM + tid];
            if (v < bv || (v == bv && ix < bi)) { bv = v; bi = ix; }
        }
        g_idx[rowBase + tid] = bi;
    }
}

// ---------------- gather ----------------
__global__ void gather_kernel(const float* __restrict__ x, const float* __restrict__ p,
                              const float* __restrict__ lab, float* __restrict__ out) {
    int row = blockIdx.x;
    int tid = threadIdx.x;
    int idx = g_idx[row];

    const float4* xr = (const float4*)(x + (size_t)row * DD);
    float4*       o0 = (float4*)(out + (size_t)row * DD);
    const float4* pr = (const float4*)(p + (size_t)idx * DD);
    float4*       o1 = (float4*)(out + (size_t)NN * DD + (size_t)row * DD);
    const float4* lr = (const float4*)(lab + (size_t)idx * CC);
    float4*       o2 = (float4*)(out + 2 * (size_t)NN * DD + (size_t)row * CC);

    if (tid < 32)       __stcs(o0 + tid,      xr[tid]);
    else if (tid < 64)  __stcs(o1 + tid - 32, pr[tid - 32]);
    for (int i = tid; i < CC / 4; i += blockDim.x) __stcs(o2 + i, lr[i]);
}

// ---------------- launch ----------------
extern "C" void kernel_launch(void* const* d_in, const int* in_sizes, int n_in,
                              void* d_out, int out_size) {
    const float* x   = (const float*)d_in[0];
    const float* p   = (const float*)d_in[1];
    const float* lab = (const float*)d_in[2];
    float* out = (float*)d_out;

    float *px2 = nullptr, *pp2 = nullptr;
    cudaGetSymbolAddress((void**)&px2, g_x2);
    cudaGetSymbolAddress((void**)&pp2, g_p2);

    cudaFuncSetAttribute(argmin_kernel, cudaFuncAttributeMaxDynamicSharedMemorySize, SMEM_BYTES);

    prep_p_kernel<<<KPAD * 16 / 256, 256>>>(p);
    row_norm_kernel<<<NN / 8, 256>>>(x, px2, NN);
    row_norm_kernel<<<(KK + 7) / 8, 256>>>(p, pp2, KK);
    argmin_kernel<<<NN / BM, NTHREADS, SMEM_BYTES>>>(x);
    gather_kernel<<<NN, 256>>>(x, p, lab, out);
}